// round 1
// baseline (speedup 1.0000x reference)
#include <cuda_runtime.h>
#include <cuda_bf16.h>

#define NN 100000
#define NE 1600000
#define HH 64
#define GG 64
#define EPS 1e-5f

// ---------------- scratch (device globals; no allocations) ----------------
__device__ float g_hs[NN * HH];      // (X@W)*dinv  (message source)
__device__ float g_a[NN * HH];       // activations a1 / a2
__device__ float g_dinv[NN];
__device__ int   g_hist[NN];
__device__ int   g_rowptr[NN + 1];
__device__ int   g_cursor[NN];
__device__ int   g_perm[NE];
__device__ int   g_bsum[128];
__device__ int   g_boff[128];
__device__ float g_red1[128];        // [sum(64), sumsq(64)] layer1
__device__ float g_red2[128];        // layer2
__device__ float g_pscale[HH], g_pshift[HH];
__device__ float g_gsum[GG * HH];
__device__ int   g_gstart[GG + 1];

// ---------------- init ----------------
__global__ void init_kernel() {
    int i = blockIdx.x * blockDim.x + threadIdx.x;
    if (i < NN) g_hist[i] = 0;
    if (i < 128) { g_red1[i] = 0.f; g_red2[i] = 0.f; }
}

__global__ void hist_kernel(const int* __restrict__ dst) {
    int e = blockIdx.x * blockDim.x + threadIdx.x;
    if (e < NE) atomicAdd(&g_hist[dst[e]], 1);
}

__global__ void dinv_kernel() {
    int i = blockIdx.x * blockDim.x + threadIdx.x;
    if (i < NN) g_dinv[i] = rsqrtf(1.0f + (float)g_hist[i]);   // +1 self loop
}

// ---------------- CSR build: blocked scan over g_hist ----------------
__global__ void scan1_kernel() {
    __shared__ int sh[1024];
    int t = threadIdx.x;
    int i = blockIdx.x * 1024 + t;
    int v = (i < NN) ? g_hist[i] : 0;
    sh[t] = v;
    __syncthreads();
    #pragma unroll
    for (int off = 1; off < 1024; off <<= 1) {
        int x = (t >= off) ? sh[t - off] : 0;
        __syncthreads();
        sh[t] += x;
        __syncthreads();
    }
    if (i < NN) g_rowptr[i] = sh[t] - v;            // block-local exclusive
    if (t == 1023) g_bsum[blockIdx.x] = sh[1023];
}

__global__ void scan2_kernel(int nb) {
    __shared__ int sh[128];
    int t = threadIdx.x;
    int v = (t < nb) ? g_bsum[t] : 0;
    sh[t] = v;
    __syncthreads();
    #pragma unroll
    for (int off = 1; off < 128; off <<= 1) {
        int x = (t >= off) ? sh[t - off] : 0;
        __syncthreads();
        sh[t] += x;
        __syncthreads();
    }
    g_boff[t] = sh[t] - v;
}

__global__ void scan3_kernel() {
    int i = blockIdx.x * blockDim.x + threadIdx.x;
    if (i < NN) {
        int r = g_rowptr[i] + g_boff[i >> 10];
        g_rowptr[i] = r;
        g_cursor[i] = r;
    }
    if (i == 0) g_rowptr[NN] = NE;
}

__global__ void fill_kernel(const int* __restrict__ src, const int* __restrict__ dst) {
    int e = blockIdx.x * blockDim.x + threadIdx.x;
    if (e < NE) {
        int d = dst[e];
        int pos = atomicAdd(&g_cursor[d], 1);
        g_perm[pos] = src[e];
    }
}

__global__ void gstart_kernel(const int* __restrict__ batch) {
    int g = threadIdx.x;
    if (g > GG) return;
    int lo = 0, hi = NN;
    while (lo < hi) {
        int mid = (lo + hi) >> 1;
        if (batch[mid] < g) lo = mid + 1; else hi = mid;
    }
    g_gstart[g] = lo;
}

// ---------------- GEMM: out[n][0:64] = (bn(in[n]) @ W) * dinv[n] ----------------
// 64x64 tile, 256 threads, 4x4 microtile, K chunked by 32.
__global__ void gemm_kernel(const float* __restrict__ Xext, int K,
                            const float* __restrict__ W, int use_bn) {
    __shared__ float Xs[64][33];
    __shared__ float Ws[32][64];
    const float* X = Xext ? Xext : g_a;
    int t = threadIdx.x;
    int tx = t & 15, ty = t >> 4;
    int row0 = blockIdx.x * 64;
    float acc[4][4] = {};
    for (int k0 = 0; k0 < K; k0 += 32) {
        #pragma unroll
        for (int i = 0; i < 8; i++) {
            int idx = t + i * 256;
            int r = idx >> 5, c = idx & 31;
            int gr = row0 + r, gk = k0 + c;
            float v = (gr < NN) ? X[gr * K + gk] : 0.f;
            if (use_bn) v = v * g_pscale[gk] + g_pshift[gk];
            Xs[r][c] = v;
        }
        #pragma unroll
        for (int i = 0; i < 8; i++) {
            int idx = t + i * 256;
            int r = idx >> 6, c = idx & 63;
            Ws[r][c] = W[(k0 + r) * 64 + c];
        }
        __syncthreads();
        #pragma unroll
        for (int kk = 0; kk < 32; kk++) {
            float a[4], w[4];
            #pragma unroll
            for (int i = 0; i < 4; i++) a[i] = Xs[ty * 4 + i][kk];
            #pragma unroll
            for (int j = 0; j < 4; j++) w[j] = Ws[kk][tx * 4 + j];
            #pragma unroll
            for (int i = 0; i < 4; i++)
                #pragma unroll
                for (int j = 0; j < 4; j++)
                    acc[i][j] += a[i] * w[j];
        }
        __syncthreads();
    }
    #pragma unroll
    for (int i = 0; i < 4; i++) {
        int r = row0 + ty * 4 + i;
        if (r < NN) {
            float dn = g_dinv[r];
            #pragma unroll
            for (int j = 0; j < 4; j++)
                g_hs[r * 64 + tx * 4 + j] = acc[i][j] * dn;
        }
    }
}

// ---------------- aggregation: a[n] = relu(dinv[n]*(hs[n] + sum_in hs[s]) + b) ----------------
__global__ void agg_kernel(const float* __restrict__ bias) {
    int warp = (blockIdx.x * blockDim.x + threadIdx.x) >> 5;
    int lane = threadIdx.x & 31;
    if (warp >= NN) return;
    int n = warp;
    const float2* h2 = (const float2*)g_hs;
    float2 acc = h2[n * 32 + lane];   // self term (hs already *dinv[src])
    int e = g_rowptr[n], end = g_rowptr[n + 1];
    while (e < end) {
        int cnt = end - e; if (cnt > 32) cnt = 32;
        int s = (lane < cnt) ? g_perm[e + lane] : 0;
        for (int i = 0; i < cnt; i++) {
            int si = __shfl_sync(0xffffffffu, s, i);
            float2 v = h2[si * 32 + lane];
            acc.x += v.x; acc.y += v.y;
        }
        e += cnt;
    }
    float dn = g_dinv[n];
    float2 bb = ((const float2*)bias)[lane];
    float2 o;
    o.x = fmaxf(acc.x * dn + bb.x, 0.f);
    o.y = fmaxf(acc.y * dn + bb.y, 0.f);
    ((float2*)g_a)[n * 32 + lane] = o;
}

// ---------------- per-channel stats over g_a -> g_red1 ----------------
__global__ void colstats_kernel() {
    __shared__ float sh[128];
    int t = threadIdx.x;
    if (t < 128) sh[t] = 0.f;
    __syncthreads();
    int c = t & 63;
    int tot = (gridDim.x * blockDim.x) >> 6;
    float s = 0.f, s2 = 0.f;
    for (int n = (blockIdx.x * blockDim.x + t) >> 6; n < NN; n += tot) {
        float v = g_a[n * 64 + c];
        s += v; s2 += v * v;
    }
    atomicAdd(&sh[c], s);
    atomicAdd(&sh[64 + c], s2);
    __syncthreads();
    if (t < 128) atomicAdd(&g_red1[t], sh[t]);
}

__global__ void bnparams_kernel(const float* __restrict__ gamma,
                                const float* __restrict__ beta) {
    int c = threadIdx.x;
    if (c >= 64) return;
    const float inv_n = 1.0f / (float)NN;
    float mu = g_red1[c] * inv_n;
    float var = g_red1[64 + c] * inv_n - mu * mu;
    float sc = gamma[c] * rsqrtf(var + EPS);
    g_pscale[c] = sc;
    g_pshift[c] = beta[c] - mu * sc;
}

// ---------------- pool: per-graph sums of g_a + global stats -> g_red2 ----------------
__global__ void pool_kernel() {
    int g = blockIdx.x;
    int n0 = g_gstart[g], n1 = g_gstart[g + 1];
    int t = threadIdx.x;
    int c = t & 63;
    float s = 0.f, s2 = 0.f;
    for (int n = n0 + (t >> 6); n < n1; n += 4) {
        float v = g_a[n * 64 + c];
        s += v; s2 += v * v;
    }
    __shared__ float sh[128];
    if (t < 128) sh[t] = 0.f;
    __syncthreads();
    atomicAdd(&sh[c], s);
    atomicAdd(&sh[64 + c], s2);
    __syncthreads();
    if (t < 64) {
        g_gsum[g * 64 + t] = sh[t];
        atomicAdd(&g_red2[t], sh[t]);
        atomicAdd(&g_red2[64 + t], sh[64 + t]);
    }
}

// ---------------- BN2 + mean + MLP head, one block per graph ----------------
__global__ void mlp_kernel(const float* __restrict__ gamma2, const float* __restrict__ beta2,
                           const float* __restrict__ fW1, const float* __restrict__ fb1,
                           const float* __restrict__ fW2, const float* __restrict__ fb2,
                           const float* __restrict__ fW3, const float* __restrict__ fb3,
                           const float* __restrict__ fW4, const float* __restrict__ fb4,
                           const float* __restrict__ oW, const float* __restrict__ ob,
                           float* __restrict__ out) {
    int g = blockIdx.x;
    int t = threadIdx.x;   // 128
    __shared__ float va[128], vb[128];
    const float inv_n = 1.0f / (float)NN;
    if (t < 64) {
        float mu = g_red2[t] * inv_n;
        float var = g_red2[64 + t] * inv_n - mu * mu;
        float sc = gamma2[t] * rsqrtf(var + EPS);
        float cnt = (float)(g_gstart[g + 1] - g_gstart[g]);
        cnt = fmaxf(cnt, 1.f);
        va[t] = (g_gsum[g * 64 + t] / cnt - mu) * sc + beta2[t];
    }
    __syncthreads();
    {   // 64 -> 128
        float acc = fb1[t];
        for (int k = 0; k < 64; k++) acc += va[k] * fW1[k * 128 + t];
        vb[t] = fmaxf(acc, 0.f);
    }
    __syncthreads();
    if (t < 64) {   // 128 -> 64
        float acc = fb2[t];
        for (int k = 0; k < 128; k++) acc += vb[k] * fW2[k * 64 + t];
        va[t] = fmaxf(acc, 0.f);
    }
    __syncthreads();
    if (t < 32) {   // 64 -> 32
        float acc = fb3[t];
        for (int k = 0; k < 64; k++) acc += va[k] * fW3[k * 32 + t];
        vb[t] = fmaxf(acc, 0.f);
    }
    __syncthreads();
    if (t < 16) {   // 32 -> 16
        float acc = fb4[t];
        for (int k = 0; k < 32; k++) acc += vb[k] * fW4[k * 16 + t];
        va[t] = fmaxf(acc, 0.f);
    }
    __syncthreads();
    if (t < 32) {   // 16 -> 1
        float p = (t < 16) ? va[t] * oW[t] : 0.f;
        #pragma unroll
        for (int off = 16; off; off >>= 1) p += __shfl_down_sync(0xffffffffu, p, off);
        if (t == 0) out[g] = p + ob[0];
    }
}

// ---------------- launch ----------------
extern "C" void kernel_launch(void* const* d_in, const int* in_sizes, int n_in,
                              void* d_out, int out_size) {
    const float* x      = (const float*)d_in[0];
    const int*   ei     = (const int*)d_in[1];
    const int*   batch  = (const int*)d_in[2];
    const float* W1     = (const float*)d_in[3];
    const float* b1     = (const float*)d_in[4];
    const float* W2     = (const float*)d_in[5];
    const float* b2     = (const float*)d_in[6];
    const float* gamma1 = (const float*)d_in[7];
    const float* beta1  = (const float*)d_in[8];
    const float* gamma2 = (const float*)d_in[9];
    const float* beta2  = (const float*)d_in[10];
    const float* fW1    = (const float*)d_in[11];
    const float* fb1    = (const float*)d_in[12];
    const float* fW2    = (const float*)d_in[13];
    const float* fb2    = (const float*)d_in[14];
    const float* fW3    = (const float*)d_in[15];
    const float* fb3    = (const float*)d_in[16];
    const float* fW4    = (const float*)d_in[17];
    const float* fb4    = (const float*)d_in[18];
    const float* oW     = (const float*)d_in[19];
    const float* ob     = (const float*)d_in[20];
    float* out = (float*)d_out;

    const int* srcp = ei;
    const int* dstp = ei + NE;

    const int nbN  = (NN + 255) / 256;
    const int nbE  = (NE + 255) / 256;
    const int nbS  = (NN + 1023) / 1024;          // 98
    const int nbG  = (NN + 63) / 64;              // 1563 GEMM tiles
    const int nbA  = (NN * 32 + 255) / 256;       // 1 warp per node, 8 warps/block

    init_kernel<<<nbN, 256>>>();
    hist_kernel<<<nbE, 256>>>(dstp);
    dinv_kernel<<<nbN, 256>>>();
    scan1_kernel<<<nbS, 1024>>>();
    scan2_kernel<<<1, 128>>>(nbS);
    scan3_kernel<<<nbN, 256>>>();
    fill_kernel<<<nbE, 256>>>(srcp, dstp);
    gstart_kernel<<<1, 128>>>(batch);

    // layer 1
    gemm_kernel<<<nbG, 256>>>(x, 128, W1, 0);     // g_hs = (x@W1)*dinv
    agg_kernel<<<nbA, 256>>>(b1);                 // g_a = relu(conv1)
    colstats_kernel<<<256, 256>>>();              // g_red1
    bnparams_kernel<<<1, 64>>>(gamma1, beta1);    // fold BN1

    // layer 2
    gemm_kernel<<<nbG, 256>>>(nullptr, 64, W2, 1);// g_hs = (bn1(a1)@W2)*dinv
    agg_kernel<<<nbA, 256>>>(b2);                 // g_a = relu(conv2)

    // head
    pool_kernel<<<GG, 256>>>();
    mlp_kernel<<<GG, 128>>>(gamma2, beta2, fW1, fb1, fW2, fb2,
                            fW3, fb3, fW4, fb4, oW, ob, out);
}

// round 3
// speedup vs baseline: 1.1926x; 1.1926x over previous
#include <cuda_runtime.h>
#include <cuda_bf16.h>

#define NN 100000
#define NE 1600000
#define HH 64
#define GG 64
#define EPS 1e-5f

// ---------------- scratch (device globals; no allocations) ----------------
__device__ float g_hs[NN * HH];      // (X@W)*dinv  (message source)
__device__ float g_a[NN * HH];       // activations a1 / a2
__device__ float g_dinv[NN];
__device__ int   g_hist[NN];
__device__ int   g_rowptr[NN + 1];
__device__ int   g_cursor[NN];
__device__ int   g_perm[NE];
__device__ int   g_bsum[128];
__device__ float g_red1[128];        // [sum(64), sumsq(64)] layer1
__device__ float g_red2[128];        // layer2
__device__ float g_pscale[HH], g_pshift[HH];
__device__ float g_gsum[GG * HH];
__device__ int   g_gstart[GG + 1];

// ---------------- helpers ----------------
__device__ __forceinline__ float f2tf(float x) {
    unsigned y;
    asm("cvt.rna.tf32.f32 %0, %1;" : "=r"(y) : "f"(x));
    return __uint_as_float(y);
}
__device__ __forceinline__ void mma_tf32(float* d, const unsigned* a, const unsigned* b) {
    asm volatile(
        "mma.sync.aligned.m16n8k8.row.col.f32.tf32.tf32.f32 "
        "{%0,%1,%2,%3}, {%4,%5,%6,%7}, {%8,%9}, {%0,%1,%2,%3};\n"
        : "+f"(d[0]), "+f"(d[1]), "+f"(d[2]), "+f"(d[3])
        : "r"(a[0]), "r"(a[1]), "r"(a[2]), "r"(a[3]), "r"(b[0]), "r"(b[1]));
}

// ---------------- init (+graph boundary search) ----------------
__global__ void init_kernel(const int* __restrict__ batch) {
    int i = blockIdx.x * 256 + threadIdx.x;
    if (i < NN) g_hist[i] = 0;
    if (i < 128) { g_red1[i] = 0.f; g_red2[i] = 0.f; }
    if (blockIdx.x == 0 && threadIdx.x <= GG) {
        int g = threadIdx.x;
        int lo = 0, hi = NN;
        while (lo < hi) {
            int mid = (lo + hi) >> 1;
            if (batch[mid] < g) lo = mid + 1; else hi = mid;
        }
        g_gstart[g] = lo;
    }
}

__global__ void hist_kernel(const int4* __restrict__ dst4) {
    int e = blockIdx.x * 256 + threadIdx.x;
    if (e < NE / 4) {
        int4 d = dst4[e];
        atomicAdd(&g_hist[d.x], 1);
        atomicAdd(&g_hist[d.y], 1);
        atomicAdd(&g_hist[d.z], 1);
        atomicAdd(&g_hist[d.w], 1);
    }
}

// ---------------- CSR build: blocked scan (+dinv fused) ----------------
__global__ void scan1_kernel() {
    __shared__ int sh[1024];
    int t = threadIdx.x;
    int i = blockIdx.x * 1024 + t;
    int v = (i < NN) ? g_hist[i] : 0;
    if (i < NN) g_dinv[i] = rsqrtf(1.0f + (float)v);
    sh[t] = v;
    __syncthreads();
    #pragma unroll
    for (int off = 1; off < 1024; off <<= 1) {
        int x = (t >= off) ? sh[t - off] : 0;
        __syncthreads();
        sh[t] += x;
        __syncthreads();
    }
    if (i < NN) g_rowptr[i] = sh[t] - v;            // block-local exclusive
    if (t == 1023) g_bsum[blockIdx.x] = sh[1023];
}

// scan of block sums done redundantly per block (98 entries, trivial)
__global__ void scan3_kernel() {
    __shared__ int sh[128], vv[128];
    const int nb = (NN + 1023) >> 10;               // 98
    int t = threadIdx.x;
    if (t < 128) { int v = (t < nb) ? g_bsum[t] : 0; sh[t] = v; vv[t] = v; }
    __syncthreads();
    #pragma unroll
    for (int off = 1; off < 128; off <<= 1) {
        int x = (t >= off && t < 128) ? sh[t - off] : 0;
        __syncthreads();
        if (t < 128) sh[t] += x;
        __syncthreads();
    }
    int bi = blockIdx.x >> 2;                       // 256 nodes/block, 1024/group
    int boff = sh[bi] - vv[bi];
    int i = blockIdx.x * 256 + t;
    if (i < NN) {
        int r = g_rowptr[i] + boff;
        g_rowptr[i] = r;
        g_cursor[i] = r;
    }
    if (i == 0) g_rowptr[NN] = NE;
}

__global__ void fill_kernel(const int4* __restrict__ src4, const int4* __restrict__ dst4) {
    int e = blockIdx.x * 256 + threadIdx.x;
    if (e < NE / 4) {
        int4 s = src4[e];
        int4 d = dst4[e];
        g_perm[atomicAdd(&g_cursor[d.x], 1)] = s.x;
        g_perm[atomicAdd(&g_cursor[d.y], 1)] = s.y;
        g_perm[atomicAdd(&g_cursor[d.z], 1)] = s.z;
        g_perm[atomicAdd(&g_cursor[d.w], 1)] = s.w;
    }
}

// ---------------- 3xTF32 MMA GEMM: g_hs[n] = (bn?(X[n]) @ W) * dinv[n] ----------------
// Block tile 128x64, 8 warps (warp tile 32x32), K chunked by 32, mma m16n8k8.
// Error-compensated: x = hi + lo, acc += hi*hi + hi*lo + lo*hi  (~fp32 accuracy).
__global__ __launch_bounds__(256) void gemm_kernel(const float* __restrict__ Xext, int K,
                                                   const float* __restrict__ W, int use_bn) {
    __shared__ float As[128][36];   // raw fp32; padded conflict-free
    __shared__ float Bs[32][68];
    const float* X = Xext ? Xext : g_a;
    int t = threadIdx.x;
    int w = t >> 5, lane = t & 31;
    int g = lane >> 2, tg = lane & 3;
    int mr = (w & 3) * 32;          // warp row offset in tile
    int nc = (w >> 2) * 32;         // warp col offset
    int row0 = blockIdx.x * 128;

    float acc[2][4][4];
    #pragma unroll
    for (int a = 0; a < 2; a++)
        #pragma unroll
        for (int b = 0; b < 4; b++)
            #pragma unroll
            for (int c = 0; c < 4; c++) acc[a][b][c] = 0.f;

    for (int k0 = 0; k0 < K; k0 += 32) {
        // load A chunk (128 x 32), optional BN fold, raw fp32 into smem
        #pragma unroll
        for (int it = 0; it < 4; it++) {
            int idx = t + it * 256;
            int r = idx >> 3, k4 = (idx & 7) * 4;
            int gr = row0 + r;
            float4 v = make_float4(0.f, 0.f, 0.f, 0.f);
            if (gr < NN) {
                v = *(const float4*)&X[gr * K + k0 + k4];
                if (use_bn) {
                    int kb = k0 + k4;
                    v.x = v.x * g_pscale[kb + 0] + g_pshift[kb + 0];
                    v.y = v.y * g_pscale[kb + 1] + g_pshift[kb + 1];
                    v.z = v.z * g_pscale[kb + 2] + g_pshift[kb + 2];
                    v.w = v.w * g_pscale[kb + 3] + g_pshift[kb + 3];
                }
            }
            *(float4*)&As[r][k4] = v;
        }
        // load B chunk (32 x 64)
        #pragma unroll
        for (int it = 0; it < 2; it++) {
            int idx = t + it * 256;
            int kk = idx >> 4, n4 = (idx & 15) * 4;
            *(float4*)&Bs[kk][n4] = *(const float4*)&W[(k0 + kk) * 64 + n4];
        }
        __syncthreads();
        #pragma unroll
        for (int ks = 0; ks < 32; ks += 8) {
            float ar[2][4], br[4][2];
            #pragma unroll
            for (int mt = 0; mt < 2; mt++) {
                int brow = mr + mt * 16;
                ar[mt][0] = As[brow + g][ks + tg];
                ar[mt][1] = As[brow + g + 8][ks + tg];
                ar[mt][2] = As[brow + g][ks + tg + 4];
                ar[mt][3] = As[brow + g + 8][ks + tg + 4];
            }
            #pragma unroll
            for (int nt = 0; nt < 4; nt++) {
                int col = nc + nt * 8 + g;
                br[nt][0] = Bs[ks + tg][col];
                br[nt][1] = Bs[ks + tg + 4][col];
            }
            // hi/lo split
            unsigned ah[2][4], al[2][4], bh[4][2], bl[4][2];
            #pragma unroll
            for (int mt = 0; mt < 2; mt++)
                #pragma unroll
                for (int i = 0; i < 4; i++) {
                    float h = f2tf(ar[mt][i]);
                    ah[mt][i] = __float_as_uint(h);
                    al[mt][i] = __float_as_uint(f2tf(ar[mt][i] - h));
                }
            #pragma unroll
            for (int nt = 0; nt < 4; nt++)
                #pragma unroll
                for (int i = 0; i < 2; i++) {
                    float h = f2tf(br[nt][i]);
                    bh[nt][i] = __float_as_uint(h);
                    bl[nt][i] = __float_as_uint(f2tf(br[nt][i] - h));
                }
            #pragma unroll
            for (int mt = 0; mt < 2; mt++)
                #pragma unroll
                for (int nt = 0; nt < 4; nt++) {
                    mma_tf32(acc[mt][nt], ah[mt], bl[nt]);   // small terms first
                    mma_tf32(acc[mt][nt], al[mt], bh[nt]);
                    mma_tf32(acc[mt][nt], ah[mt], bh[nt]);
                }
        }
        __syncthreads();
    }

    // epilogue: * dinv[row], write g_hs
    #pragma unroll
    for (int mt = 0; mt < 2; mt++) {
        int r0g = row0 + mr + mt * 16 + g;
        int r1g = r0g + 8;
        float dn0 = (r0g < NN) ? g_dinv[r0g] : 0.f;
        float dn1 = (r1g < NN) ? g_dinv[r1g] : 0.f;
        #pragma unroll
        for (int nt = 0; nt < 4; nt++) {
            int col = nc + nt * 8 + tg * 2;
            if (r0g < NN) {
                float2 o = make_float2(acc[mt][nt][0] * dn0, acc[mt][nt][1] * dn0);
                *(float2*)&g_hs[r0g * 64 + col] = o;
            }
            if (r1g < NN) {
                float2 o = make_float2(acc[mt][nt][2] * dn1, acc[mt][nt][3] * dn1);
                *(float2*)&g_hs[r1g * 64 + col] = o;
            }
        }
    }
}

// ---------------- aggregation: a[n] = relu(dinv[n]*(hs[n] + sum_in hs[s]) + b) ----------------
__global__ void agg_kernel(const float* __restrict__ bias) {
    int warp = (blockIdx.x * blockDim.x + threadIdx.x) >> 5;
    int lane = threadIdx.x & 31;
    if (warp >= NN) return;
    int n = warp;
    const float2* h2 = (const float2*)g_hs;
    float2 acc = h2[n * 32 + lane];   // self term (hs already *dinv[src])
    int e = g_rowptr[n], end = g_rowptr[n + 1];
    while (e < end) {
        int cnt = end - e; if (cnt > 32) cnt = 32;
        int s = (lane < cnt) ? g_perm[e + lane] : 0;
        int i = 0;
        for (; i + 4 <= cnt; i += 4) {
            int s0 = __shfl_sync(0xffffffffu, s, i);
            int s1 = __shfl_sync(0xffffffffu, s, i + 1);
            int s2 = __shfl_sync(0xffffffffu, s, i + 2);
            int s3 = __shfl_sync(0xffffffffu, s, i + 3);
            float2 v0 = h2[s0 * 32 + lane];
            float2 v1 = h2[s1 * 32 + lane];
            float2 v2 = h2[s2 * 32 + lane];
            float2 v3 = h2[s3 * 32 + lane];
            acc.x += (v0.x + v1.x) + (v2.x + v3.x);
            acc.y += (v0.y + v1.y) + (v2.y + v3.y);
        }
        for (; i < cnt; i++) {
            int si = __shfl_sync(0xffffffffu, s, i);
            float2 v = h2[si * 32 + lane];
            acc.x += v.x; acc.y += v.y;
        }
        e += cnt;
    }
    float dn = g_dinv[n];
    float2 bb = ((const float2*)bias)[lane];
    float2 o;
    o.x = fmaxf(acc.x * dn + bb.x, 0.f);
    o.y = fmaxf(acc.y * dn + bb.y, 0.f);
    ((float2*)g_a)[n * 32 + lane] = o;
}

// ---------------- per-channel stats over g_a -> g_red1 ----------------
__global__ void colstats_kernel() {
    __shared__ float sh[128];
    int t = threadIdx.x;
    if (t < 128) sh[t] = 0.f;
    __syncthreads();
    int c = t & 63;
    int tot = (gridDim.x * blockDim.x) >> 6;
    float s = 0.f, s2 = 0.f;
    for (int n = (blockIdx.x * blockDim.x + t) >> 6; n < NN; n += tot) {
        float v = g_a[n * 64 + c];
        s += v; s2 += v * v;
    }
    atomicAdd(&sh[c], s);
    atomicAdd(&sh[64 + c], s2);
    __syncthreads();
    if (t < 128) atomicAdd(&g_red1[t], sh[t]);
}

__global__ void bnparams_kernel(const float* __restrict__ gamma,
                                const float* __restrict__ beta) {
    int c = threadIdx.x;
    if (c >= 64) return;
    const float inv_n = 1.0f / (float)NN;
    float mu = g_red1[c] * inv_n;
    float var = g_red1[64 + c] * inv_n - mu * mu;
    float sc = gamma[c] * rsqrtf(var + EPS);
    g_pscale[c] = sc;
    g_pshift[c] = beta[c] - mu * sc;
}

// ---------------- pool: per-graph sums of g_a + global stats -> g_red2 ----------------
__global__ void pool_kernel() {
    int g = blockIdx.x;
    int n0 = g_gstart[g], n1 = g_gstart[g + 1];
    int t = threadIdx.x;
    int c = t & 63;
    float s = 0.f, s2 = 0.f;
    for (int n = n0 + (t >> 6); n < n1; n += 4) {
        float v = g_a[n * 64 + c];
        s += v; s2 += v * v;
    }
    __shared__ float sh[128];
    if (t < 128) sh[t] = 0.f;
    __syncthreads();
    atomicAdd(&sh[c], s);
    atomicAdd(&sh[64 + c], s2);
    __syncthreads();
    if (t < 64) {
        g_gsum[g * 64 + t] = sh[t];
        atomicAdd(&g_red2[t], sh[t]);
        atomicAdd(&g_red2[64 + t], sh[64 + t]);
    }
}

// ---------------- BN2 + mean + MLP head, one block per graph ----------------
__global__ void mlp_kernel(const float* __restrict__ gamma2, const float* __restrict__ beta2,
                           const float* __restrict__ fW1, const float* __restrict__ fb1,
                           const float* __restrict__ fW2, const float* __restrict__ fb2,
                           const float* __restrict__ fW3, const float* __restrict__ fb3,
                           const float* __restrict__ fW4, const float* __restrict__ fb4,
                           const float* __restrict__ oW, const float* __restrict__ ob,
                           float* __restrict__ out) {
    int g = blockIdx.x;
    int t = threadIdx.x;   // 128
    __shared__ float va[128], vb[128];
    const float inv_n = 1.0f / (float)NN;
    if (t < 64) {
        float mu = g_red2[t] * inv_n;
        float var = g_red2[64 + t] * inv_n - mu * mu;
        float sc = gamma2[t] * rsqrtf(var + EPS);
        float cnt = (float)(g_gstart[g + 1] - g_gstart[g]);
        cnt = fmaxf(cnt, 1.f);
        va[t] = (g_gsum[g * 64 + t] / cnt - mu) * sc + beta2[t];
    }
    __syncthreads();
    {   // 64 -> 128
        float acc = fb1[t];
        for (int k = 0; k < 64; k++) acc += va[k] * fW1[k * 128 + t];
        vb[t] = fmaxf(acc, 0.f);
    }
    __syncthreads();
    if (t < 64) {   // 128 -> 64
        float acc = fb2[t];
        for (int k = 0; k < 128; k++) acc += vb[k] * fW2[k * 64 + t];
        va[t] = fmaxf(acc, 0.f);
    }
    __syncthreads();
    if (t < 32) {   // 64 -> 32
        float acc = fb3[t];
        for (int k = 0; k < 64; k++) acc += va[k] * fW3[k * 32 + t];
        vb[t] = fmaxf(acc, 0.f);
    }
    __syncthreads();
    if (t < 16) {   // 32 -> 16
        float acc = fb4[t];
        for (int k = 0; k < 32; k++) acc += vb[k] * fW4[k * 16 + t];
        va[t] = fmaxf(acc, 0.f);
    }
    __syncthreads();
    if (t < 32) {   // 16 -> 1
        float p = (t < 16) ? va[t] * oW[t] : 0.f;
        #pragma unroll
        for (int off = 16; off; off >>= 1) p += __shfl_down_sync(0xffffffffu, p, off);
        if (t == 0) out[g] = p + ob[0];
    }
}

// ---------------- launch ----------------
extern "C" void kernel_launch(void* const* d_in, const int* in_sizes, int n_in,
                              void* d_out, int out_size) {
    const float* x      = (const float*)d_in[0];
    const int*   ei     = (const int*)d_in[1];
    const int*   batch  = (const int*)d_in[2];
    const float* W1     = (const float*)d_in[3];
    const float* b1     = (const float*)d_in[4];
    const float* W2     = (const float*)d_in[5];
    const float* b2     = (const float*)d_in[6];
    const float* gamma1 = (const float*)d_in[7];
    const float* beta1  = (const float*)d_in[8];
    const float* gamma2 = (const float*)d_in[9];
    const float* beta2  = (const float*)d_in[10];
    const float* fW1    = (const float*)d_in[11];
    const float* fb1    = (const float*)d_in[12];
    const float* fW2    = (const float*)d_in[13];
    const float* fb2    = (const float*)d_in[14];
    const float* fW3    = (const float*)d_in[15];
    const float* fb3    = (const float*)d_in[16];
    const float* fW4    = (const float*)d_in[17];
    const float* fb4    = (const float*)d_in[18];
    const float* oW     = (const float*)d_in[19];
    const float* ob     = (const float*)d_in[20];
    float* out = (float*)d_out;

    const int4* src4 = (const int4*)ei;
    const int4* dst4 = (const int4*)(ei + NE);

    const int nbN  = (NN + 255) / 256;            // 391
    const int nbE4 = (NE / 4 + 255) / 256;        // 1563
    const int nbS  = (NN + 1023) / 1024;          // 98
    const int nbG  = (NN + 127) / 128;            // 782 GEMM tiles
    const int nbA  = (NN * 32 + 255) / 256;       // 1 warp per node

    init_kernel<<<nbN, 256>>>(batch);             // 0
    hist_kernel<<<nbE4, 256>>>(dst4);             // 1
    scan1_kernel<<<nbS, 1024>>>();                // 2 (+dinv)
    scan3_kernel<<<nbN, 256>>>();                 // 3 (inline top scan)
    fill_kernel<<<nbE4, 256>>>(src4, dst4);       // 4

    // layer 1
    gemm_kernel<<<nbG, 256>>>(x, 128, W1, 0);     // 5  <- profiled slot
    agg_kernel<<<nbA, 256>>>(b1);                 // 6
    colstats_kernel<<<256, 256>>>();              // 7
    bnparams_kernel<<<1, 64>>>(gamma1, beta1);    // 8

    // layer 2
    gemm_kernel<<<nbG, 256>>>(nullptr, 64, W2, 1);// 9
    agg_kernel<<<nbA, 256>>>(b2);                 // 10

    // head
    pool_kernel<<<GG, 256>>>();                   // 11
    mlp_kernel<<<GG, 128>>>(gamma2, beta2, fW1, fb1, fW2, fb2,
                            fW3, fb3, fW4, fb4, oW, ob, out);  // 12
}

// round 4
// speedup vs baseline: 1.2052x; 1.0105x over previous
#include <cuda_runtime.h>
#include <cuda_bf16.h>
#include <cuda_fp16.h>

#define NN 100000
#define NE 1600000
#define HH 64
#define GG 64
#define EPS 1e-5f

// ---------------- scratch (device globals; no allocations) ----------------
__device__ __half g_hs[NN * HH];     // (X@W)*dinv as fp16 (message source)
__device__ float g_a[NN * HH];       // activations a1 / a2 (fp32)
__device__ float g_dinv[NN];
__device__ int   g_hist[NN];
__device__ int   g_rowptr[NN + 1];
__device__ int   g_cursor[NN];
__device__ int   g_perm[NE];
__device__ int   g_bsum[128];
__device__ float g_red1[128];        // [sum(64), sumsq(64)] layer1
__device__ float g_red2[128];        // layer2
__device__ int   g_ctr1;             // last-block-done counter for colstats
__device__ float g_pscale[HH], g_pshift[HH];
__device__ float g_gsum[GG * HH];
__device__ int   g_gstart[GG + 1];

// ---------------- helpers ----------------
__device__ __forceinline__ float f2tf(float x) {
    unsigned y;
    asm("cvt.rna.tf32.f32 %0, %1;" : "=r"(y) : "f"(x));
    return __uint_as_float(y);
}
__device__ __forceinline__ void mma_tf32(float* d, const unsigned* a, const unsigned* b) {
    asm volatile(
        "mma.sync.aligned.m16n8k8.row.col.f32.tf32.tf32.f32 "
        "{%0,%1,%2,%3}, {%4,%5,%6,%7}, {%8,%9}, {%0,%1,%2,%3};\n"
        : "+f"(d[0]), "+f"(d[1]), "+f"(d[2]), "+f"(d[3])
        : "r"(a[0]), "r"(a[1]), "r"(a[2]), "r"(a[3]), "r"(b[0]), "r"(b[1]));
}

// ---------------- init (+graph boundary search) ----------------
__global__ void init_kernel(const int* __restrict__ batch) {
    int i = blockIdx.x * 256 + threadIdx.x;
    if (i < NN) g_hist[i] = 0;
    if (i < 128) { g_red1[i] = 0.f; g_red2[i] = 0.f; }
    if (i == 0) g_ctr1 = 0;
    if (blockIdx.x == 0 && threadIdx.x <= GG) {
        int g = threadIdx.x;
        int lo = 0, hi = NN;
        while (lo < hi) {
            int mid = (lo + hi) >> 1;
            if (batch[mid] < g) lo = mid + 1; else hi = mid;
        }
        g_gstart[g] = lo;
    }
}

__global__ void hist_kernel(const int4* __restrict__ dst4) {
    int e = blockIdx.x * 256 + threadIdx.x;
    if (e < NE / 4) {
        int4 d = dst4[e];
        atomicAdd(&g_hist[d.x], 1);
        atomicAdd(&g_hist[d.y], 1);
        atomicAdd(&g_hist[d.z], 1);
        atomicAdd(&g_hist[d.w], 1);
    }
}

// ---------------- CSR build: blocked scan (+dinv fused) ----------------
__global__ void scan1_kernel() {
    __shared__ int sh[1024];
    int t = threadIdx.x;
    int i = blockIdx.x * 1024 + t;
    int v = (i < NN) ? g_hist[i] : 0;
    if (i < NN) g_dinv[i] = rsqrtf(1.0f + (float)v);
    sh[t] = v;
    __syncthreads();
    #pragma unroll
    for (int off = 1; off < 1024; off <<= 1) {
        int x = (t >= off) ? sh[t - off] : 0;
        __syncthreads();
        sh[t] += x;
        __syncthreads();
    }
    if (i < NN) g_rowptr[i] = sh[t] - v;            // block-local exclusive
    if (t == 1023) g_bsum[blockIdx.x] = sh[1023];
}

// scan of the 98 block sums done redundantly per block; 98 blocks x 1024 thr
__global__ void scan3_kernel() {
    __shared__ int sh[128], vv[128];
    const int nb = (NN + 1023) >> 10;               // 98
    int t = threadIdx.x;
    if (t < 128) { int v = (t < nb) ? g_bsum[t] : 0; sh[t] = v; vv[t] = v; }
    __syncthreads();
    #pragma unroll
    for (int off = 1; off < 128; off <<= 1) {
        int x = (t >= off && t < 128) ? sh[t - off] : 0;
        __syncthreads();
        if (t < 128) sh[t] += x;
        __syncthreads();
    }
    int boff = sh[blockIdx.x] - vv[blockIdx.x];
    int i = blockIdx.x * 1024 + t;
    if (i < NN) {
        int r = g_rowptr[i] + boff;
        g_rowptr[i] = r;
        g_cursor[i] = r;
    }
    if (i == 0) g_rowptr[NN] = NE;
}

__global__ void fill_kernel(const int4* __restrict__ src4, const int4* __restrict__ dst4) {
    int e = blockIdx.x * 256 + threadIdx.x;
    if (e < NE / 4) {
        int4 s = src4[e];
        int4 d = dst4[e];
        g_perm[atomicAdd(&g_cursor[d.x], 1)] = s.x;
        g_perm[atomicAdd(&g_cursor[d.y], 1)] = s.y;
        g_perm[atomicAdd(&g_cursor[d.z], 1)] = s.z;
        g_perm[atomicAdd(&g_cursor[d.w], 1)] = s.w;
    }
}

// ---------------- 3xTF32 MMA GEMM: g_hs[n] = half((bn?(X[n]) @ W) * dinv[n]) ----------------
// Block tile 128x64, 8 warps (warp tile 32x32), K chunked by 32, mma m16n8k8.
__global__ __launch_bounds__(256) void gemm_kernel(const float* __restrict__ Xext, int K,
                                                   const float* __restrict__ W, int use_bn) {
    __shared__ float As[128][36];   // raw fp32; padded conflict-free
    __shared__ float Bs[32][68];
    const float* X = Xext ? Xext : g_a;
    int t = threadIdx.x;
    int w = t >> 5, lane = t & 31;
    int g = lane >> 2, tg = lane & 3;
    int mr = (w & 3) * 32;          // warp row offset in tile
    int nc = (w >> 2) * 32;         // warp col offset
    int row0 = blockIdx.x * 128;

    float acc[2][4][4];
    #pragma unroll
    for (int a = 0; a < 2; a++)
        #pragma unroll
        for (int b = 0; b < 4; b++)
            #pragma unroll
            for (int c = 0; c < 4; c++) acc[a][b][c] = 0.f;

    for (int k0 = 0; k0 < K; k0 += 32) {
        #pragma unroll
        for (int it = 0; it < 4; it++) {
            int idx = t + it * 256;
            int r = idx >> 3, k4 = (idx & 7) * 4;
            int gr = row0 + r;
            float4 v = make_float4(0.f, 0.f, 0.f, 0.f);
            if (gr < NN) {
                v = *(const float4*)&X[gr * K + k0 + k4];
                if (use_bn) {
                    int kb = k0 + k4;
                    v.x = v.x * g_pscale[kb + 0] + g_pshift[kb + 0];
                    v.y = v.y * g_pscale[kb + 1] + g_pshift[kb + 1];
                    v.z = v.z * g_pscale[kb + 2] + g_pshift[kb + 2];
                    v.w = v.w * g_pscale[kb + 3] + g_pshift[kb + 3];
                }
            }
            *(float4*)&As[r][k4] = v;
        }
        #pragma unroll
        for (int it = 0; it < 2; it++) {
            int idx = t + it * 256;
            int kk = idx >> 4, n4 = (idx & 15) * 4;
            *(float4*)&Bs[kk][n4] = *(const float4*)&W[(k0 + kk) * 64 + n4];
        }
        __syncthreads();
        #pragma unroll
        for (int ks = 0; ks < 32; ks += 8) {
            float ar[2][4], br[4][2];
            #pragma unroll
            for (int mt = 0; mt < 2; mt++) {
                int brow = mr + mt * 16;
                ar[mt][0] = As[brow + g][ks + tg];
                ar[mt][1] = As[brow + g + 8][ks + tg];
                ar[mt][2] = As[brow + g][ks + tg + 4];
                ar[mt][3] = As[brow + g + 8][ks + tg + 4];
            }
            #pragma unroll
            for (int nt = 0; nt < 4; nt++) {
                int col = nc + nt * 8 + g;
                br[nt][0] = Bs[ks + tg][col];
                br[nt][1] = Bs[ks + tg + 4][col];
            }
            unsigned ah[2][4], al[2][4], bh[4][2], bl[4][2];
            #pragma unroll
            for (int mt = 0; mt < 2; mt++)
                #pragma unroll
                for (int i = 0; i < 4; i++) {
                    float h = f2tf(ar[mt][i]);
                    ah[mt][i] = __float_as_uint(h);
                    al[mt][i] = __float_as_uint(f2tf(ar[mt][i] - h));
                }
            #pragma unroll
            for (int nt = 0; nt < 4; nt++)
                #pragma unroll
                for (int i = 0; i < 2; i++) {
                    float h = f2tf(br[nt][i]);
                    bh[nt][i] = __float_as_uint(h);
                    bl[nt][i] = __float_as_uint(f2tf(br[nt][i] - h));
                }
            #pragma unroll
            for (int mt = 0; mt < 2; mt++)
                #pragma unroll
                for (int nt = 0; nt < 4; nt++) {
                    mma_tf32(acc[mt][nt], ah[mt], bl[nt]);
                    mma_tf32(acc[mt][nt], al[mt], bh[nt]);
                    mma_tf32(acc[mt][nt], ah[mt], bh[nt]);
                }
        }
        __syncthreads();
    }

    // epilogue: * dinv[row], convert to half2, write g_hs
    #pragma unroll
    for (int mt = 0; mt < 2; mt++) {
        int r0g = row0 + mr + mt * 16 + g;
        int r1g = r0g + 8;
        float dn0 = (r0g < NN) ? g_dinv[r0g] : 0.f;
        float dn1 = (r1g < NN) ? g_dinv[r1g] : 0.f;
        #pragma unroll
        for (int nt = 0; nt < 4; nt++) {
            int col = nc + nt * 8 + tg * 2;
            if (r0g < NN) {
                __half2 o = __float22half2_rn(make_float2(acc[mt][nt][0] * dn0,
                                                          acc[mt][nt][1] * dn0));
                *(__half2*)&g_hs[r0g * 64 + col] = o;
            }
            if (r1g < NN) {
                __half2 o = __float22half2_rn(make_float2(acc[mt][nt][2] * dn1,
                                                          acc[mt][nt][3] * dn1));
                *(__half2*)&g_hs[r1g * 64 + col] = o;
            }
        }
    }
}

// ---------------- aggregation: a[n] = relu(dinv[n]*(hs[n] + sum_in hs[s]) + b) ----------------
__global__ void agg_kernel(const float* __restrict__ bias) {
    int warp = (blockIdx.x * blockDim.x + threadIdx.x) >> 5;
    int lane = threadIdx.x & 31;
    if (warp >= NN) return;
    int n = warp;
    const __half2* h2 = (const __half2*)g_hs;
    float2 acc = __half22float2(h2[n * 32 + lane]);   // self term
    int e = g_rowptr[n], end = g_rowptr[n + 1];
    while (e < end) {
        int cnt = end - e; if (cnt > 32) cnt = 32;
        int s = (lane < cnt) ? g_perm[e + lane] : 0;
        int i = 0;
        for (; i + 8 <= cnt; i += 8) {
            int s0 = __shfl_sync(0xffffffffu, s, i);
            int s1 = __shfl_sync(0xffffffffu, s, i + 1);
            int s2 = __shfl_sync(0xffffffffu, s, i + 2);
            int s3 = __shfl_sync(0xffffffffu, s, i + 3);
            int s4 = __shfl_sync(0xffffffffu, s, i + 4);
            int s5 = __shfl_sync(0xffffffffu, s, i + 5);
            int s6 = __shfl_sync(0xffffffffu, s, i + 6);
            int s7 = __shfl_sync(0xffffffffu, s, i + 7);
            __half2 v0 = h2[s0 * 32 + lane];
            __half2 v1 = h2[s1 * 32 + lane];
            __half2 v2 = h2[s2 * 32 + lane];
            __half2 v3 = h2[s3 * 32 + lane];
            __half2 v4 = h2[s4 * 32 + lane];
            __half2 v5 = h2[s5 * 32 + lane];
            __half2 v6 = h2[s6 * 32 + lane];
            __half2 v7 = h2[s7 * 32 + lane];
            float2 f0 = __half22float2(v0), f1 = __half22float2(v1);
            float2 f2 = __half22float2(v2), f3 = __half22float2(v3);
            float2 f4 = __half22float2(v4), f5 = __half22float2(v5);
            float2 f6 = __half22float2(v6), f7 = __half22float2(v7);
            acc.x += ((f0.x + f1.x) + (f2.x + f3.x)) + ((f4.x + f5.x) + (f6.x + f7.x));
            acc.y += ((f0.y + f1.y) + (f2.y + f3.y)) + ((f4.y + f5.y) + (f6.y + f7.y));
        }
        for (; i < cnt; i++) {
            int si = __shfl_sync(0xffffffffu, s, i);
            float2 f = __half22float2(h2[si * 32 + lane]);
            acc.x += f.x; acc.y += f.y;
        }
        e += cnt;
    }
    float dn = g_dinv[n];
    float2 bb = ((const float2*)bias)[lane];
    float2 o;
    o.x = fmaxf(acc.x * dn + bb.x, 0.f);
    o.y = fmaxf(acc.y * dn + bb.y, 0.f);
    ((float2*)g_a)[n * 32 + lane] = o;
}

// ---------------- per-channel stats over g_a -> g_red1, + fused BN-param compute ----------------
__global__ void colstats_kernel(const float* __restrict__ gamma,
                                const float* __restrict__ beta) {
    __shared__ float sh[128];
    __shared__ int isLast;
    int t = threadIdx.x;
    if (t < 128) sh[t] = 0.f;
    __syncthreads();
    int c = t & 63;
    int tot = (gridDim.x * blockDim.x) >> 6;
    float s = 0.f, s2 = 0.f;
    for (int n = (blockIdx.x * blockDim.x + t) >> 6; n < NN; n += tot) {
        float v = g_a[n * 64 + c];
        s += v; s2 += v * v;
    }
    atomicAdd(&sh[c], s);
    atomicAdd(&sh[64 + c], s2);
    __syncthreads();
    if (t < 128) atomicAdd(&g_red1[t], sh[t]);
    __threadfence();
    if (t == 0) {
        int done = atomicAdd(&g_ctr1, 1);
        isLast = (done == (int)gridDim.x - 1);
    }
    __syncthreads();
    if (isLast && t < 64) {
        __threadfence();
        const float inv_n = 1.0f / (float)NN;
        float sum = atomicAdd(&g_red1[t], 0.f);       // coherent L2 read
        float ssq = atomicAdd(&g_red1[64 + t], 0.f);
        float mu = sum * inv_n;
        float var = ssq * inv_n - mu * mu;
        float sc = gamma[t] * rsqrtf(var + EPS);
        g_pscale[t] = sc;
        g_pshift[t] = beta[t] - mu * sc;
    }
}

// ---------------- pool: per-graph sums of g_a + global stats -> g_red2 ----------------
__global__ void pool_kernel() {
    int g = blockIdx.x;
    int n0 = g_gstart[g], n1 = g_gstart[g + 1];
    int t = threadIdx.x;
    int c = t & 63;
    float s = 0.f, s2 = 0.f;
    for (int n = n0 + (t >> 6); n < n1; n += 4) {
        float v = g_a[n * 64 + c];
        s += v; s2 += v * v;
    }
    __shared__ float sh[128];
    if (t < 128) sh[t] = 0.f;
    __syncthreads();
    atomicAdd(&sh[c], s);
    atomicAdd(&sh[64 + c], s2);
    __syncthreads();
    if (t < 64) {
        g_gsum[g * 64 + t] = sh[t];
        atomicAdd(&g_red2[t], sh[t]);
        atomicAdd(&g_red2[64 + t], sh[64 + t]);
    }
}

// ---------------- BN2 + mean + MLP head, one block per graph ----------------
__global__ void mlp_kernel(const float* __restrict__ gamma2, const float* __restrict__ beta2,
                           const float* __restrict__ fW1, const float* __restrict__ fb1,
                           const float* __restrict__ fW2, const float* __restrict__ fb2,
                           const float* __restrict__ fW3, const float* __restrict__ fb3,
                           const float* __restrict__ fW4, const float* __restrict__ fb4,
                           const float* __restrict__ oW, const float* __restrict__ ob,
                           float* __restrict__ out) {
    int g = blockIdx.x;
    int t = threadIdx.x;   // 128
    __shared__ float va[128], vb[128];
    const float inv_n = 1.0f / (float)NN;
    if (t < 64) {
        float mu = g_red2[t] * inv_n;
        float var = g_red2[64 + t] * inv_n - mu * mu;
        float sc = gamma2[t] * rsqrtf(var + EPS);
        float cnt = (float)(g_gstart[g + 1] - g_gstart[g]);
        cnt = fmaxf(cnt, 1.f);
        va[t] = (g_gsum[g * 64 + t] / cnt - mu) * sc + beta2[t];
    }
    __syncthreads();
    {   // 64 -> 128
        float acc = fb1[t];
        for (int k = 0; k < 64; k++) acc += va[k] * fW1[k * 128 + t];
        vb[t] = fmaxf(acc, 0.f);
    }
    __syncthreads();
    if (t < 64) {   // 128 -> 64
        float acc = fb2[t];
        for (int k = 0; k < 128; k++) acc += vb[k] * fW2[k * 64 + t];
        va[t] = fmaxf(acc, 0.f);
    }
    __syncthreads();
    if (t < 32) {   // 64 -> 32
        float acc = fb3[t];
        for (int k = 0; k < 64; k++) acc += va[k] * fW3[k * 32 + t];
        vb[t] = fmaxf(acc, 0.f);
    }
    __syncthreads();
    if (t < 16) {   // 32 -> 16
        float acc = fb4[t];
        for (int k = 0; k < 32; k++) acc += vb[k] * fW4[k * 16 + t];
        va[t] = fmaxf(acc, 0.f);
    }
    __syncthreads();
    if (t < 32) {   // 16 -> 1
        float p = (t < 16) ? va[t] * oW[t] : 0.f;
        #pragma unroll
        for (int off = 16; off; off >>= 1) p += __shfl_down_sync(0xffffffffu, p, off);
        if (t == 0) out[g] = p + ob[0];
    }
}

// ---------------- launch ----------------
extern "C" void kernel_launch(void* const* d_in, const int* in_sizes, int n_in,
                              void* d_out, int out_size) {
    const float* x      = (const float*)d_in[0];
    const int*   ei     = (const int*)d_in[1];
    const int*   batch  = (const int*)d_in[2];
    const float* W1     = (const float*)d_in[3];
    const float* b1     = (const float*)d_in[4];
    const float* W2     = (const float*)d_in[5];
    const float* b2     = (const float*)d_in[6];
    const float* gamma1 = (const float*)d_in[7];
    const float* beta1  = (const float*)d_in[8];
    const float* gamma2 = (const float*)d_in[9];
    const float* beta2  = (const float*)d_in[10];
    const float* fW1    = (const float*)d_in[11];
    const float* fb1    = (const float*)d_in[12];
    const float* fW2    = (const float*)d_in[13];
    const float* fb2    = (const float*)d_in[14];
    const float* fW3    = (const float*)d_in[15];
    const float* fb3    = (const float*)d_in[16];
    const float* fW4    = (const float*)d_in[17];
    const float* fb4    = (const float*)d_in[18];
    const float* oW     = (const float*)d_in[19];
    const float* ob     = (const float*)d_in[20];
    float* out = (float*)d_out;

    const int4* src4 = (const int4*)ei;
    const int4* dst4 = (const int4*)(ei + NE);

    const int nbN  = (NN + 255) / 256;            // 391
    const int nbE4 = (NE / 4 + 255) / 256;        // 1563
    const int nbS  = (NN + 1023) / 1024;          // 98
    const int nbG  = (NN + 127) / 128;            // 782 GEMM tiles
    const int nbA  = (NN * 32 + 255) / 256;       // 1 warp per node

    init_kernel<<<nbN, 256>>>(batch);             // 0
    hist_kernel<<<nbE4, 256>>>(dst4);             // 1
    scan1_kernel<<<nbS, 1024>>>();                // 2 (+dinv)
    scan3_kernel<<<nbS, 1024>>>();                // 3 (inline top scan)
    fill_kernel<<<nbE4, 256>>>(src4, dst4);       // 4

    // layer 1
    gemm_kernel<<<nbG, 256>>>(x, 128, W1, 0);     // 5
    agg_kernel<<<nbA, 256>>>(b1);                 // 6
    colstats_kernel<<<256, 256>>>(gamma1, beta1); // 7 (+fused bnparams)

    // layer 2
    gemm_kernel<<<nbG, 256>>>(nullptr, 64, W2, 1);// 8
    agg_kernel<<<nbA, 256>>>(b2);                 // 9

    // head
    pool_kernel<<<GG, 256>>>();                   // 10
    mlp_kernel<<<GG, 128>>>(gamma2, beta2, fW1, fb1, fW2, fb2,
                            fW3, fb3, fW4, fb4, oW, ob, out);  // 11
}